// round 13
// baseline (speedup 1.0000x reference)
#include <cuda_runtime.h>
#include <cstdint>
#include <math_constants.h>

#define B      128
#define HH     400
#define WW     400
#define HW     160000
#define WPR    13
#define NWORDS 5200
#define NA     2500
#define NP     20000
#define NI     (HW - NP)
#define CAND_CAP 16384
#define CBUF_CAP 1024
// sampling: 12.5% in coalesced runs of 32 float4 per 256-float4 window
#define NS4    5000
#define STARGET 625
// candidate pass chunking
#define CPB2   20
#define CH4B   (HW / 4 / CPB2)      // 2000

// Output layout: flat f32 concat of (out_idx, query_pos, new_mask, xy_vox_idx, ignore_idx)
#define OI_OFF 0l
#define QP_OFF 2560000l
#define NM_OFF 33280000l
#define XY_OFF 53760000l
#define IG_OFF 58880000l

__device__ uint32_t g_p1[B];
__device__ int      g_cnt[B];
__device__ int      g_done[B];
__device__ uint2    g_cand[B][CAND_CAP];      // {key, idx}
__device__ uint32_t g_dil[B * NWORDS];
__device__ int      g_prefix[B * NWORDS];
__device__ int      g_total[B];
__device__ float2   g_selgrid[B][NP];

__device__ __forceinline__ uint32_t mono_key(float v) {
    uint32_t u = __float_as_uint(v);
    return (u & 0x80000000u) ? ~u : (u | 0x80000000u);
}

__device__ __forceinline__ uint32_t score_key(float p, float m) {
    if (m == 1.0f) return mono_key(p);
    if (m == 0.0f) return mono_key(-CUDART_INF_F);
    float s = __fdividef(1.0f, 1.0f + __expf(-p)) * m;
    float pe;
    if (s <= 0.0f)      pe = -CUDART_INF_F;
    else if (s >= 1.0f) pe =  CUDART_INF_F;
    else                pe = __logf(s) - __logf(1.0f - s);
    return mono_key(pe);
}

// Warp-serial suffix select (warp 0 only). Largest digit d with
// sum_{d'>=d} hist[d'] >= rem; *s_rem = rem - sum_{d'>d}.
__device__ __forceinline__ void warp_suffix_select(const uint32_t* hist, int nbins,
                                                   uint32_t rem,
                                                   volatile uint32_t* s_dig,
                                                   volatile uint32_t* s_rem)
{
    const int lane = threadIdx.x & 31;
    const int per = nbins >> 5;
    uint32_t lsum = 0;
    for (int k = 0; k < per; k++) {
        int kk = (k + lane) & (per - 1);
        lsum += hist[lane * per + kk];
    }
    uint32_t suf = lsum;
    #pragma unroll
    for (int o = 1; o < 32; o <<= 1) {
        uint32_t n = __shfl_down_sync(0xffffffffu, suf, o);
        if (lane + o < 32) suf += n;
    }
    uint32_t sufnext = suf - lsum;
    bool mine = (suf >= rem) && (sufnext < rem);
    if (mine) {
        uint32_t acc = sufnext;
        for (int k = per - 1; k >= 0; k--) {
            uint32_t h = hist[lane * per + k];
            acc += h;
            if (acc >= rem) { *s_dig = (uint32_t)(lane * per + k); *s_rem = rem - (acc - h); break; }
        }
    }
}

// ---------------------------------------------------------------------------
// K_A: sampled histogram (coalesced 32-float4 runs, 12.5%) -> conservative
// pivot digit. Also resets per-batch counters. grid B x 256
// ---------------------------------------------------------------------------
__global__ __launch_bounds__(256) void k_sample(const float* __restrict__ pred,
                                                const float* __restrict__ mask)
{
    __shared__ uint32_t hist[2048];
    __shared__ uint32_t s_dig, s_rem;
    const int b = blockIdx.x, tid = threadIdx.x;
    for (int i = tid; i < 2048; i += 256) hist[i] = 0;
    __syncthreads();

    const float4* p4 = (const float4*)(pred + (size_t)b * HW);
    const float4* m4 = (const float4*)(mask + (size_t)b * HW);
    for (int s = tid; s < NS4; s += 256) {
        int v = ((s & ~31) << 3) + (s & 31);      // 32-consecutive runs, coalesced
        float4 pv = __ldg(&p4[v]);
        float4 mv = __ldg(&m4[v]);
        atomicAdd(&hist[score_key(pv.x, mv.x) >> 21], 1u);
        atomicAdd(&hist[score_key(pv.y, mv.y) >> 21], 1u);
        atomicAdd(&hist[score_key(pv.z, mv.z) >> 21], 1u);
        atomicAdd(&hist[score_key(pv.w, mv.w) >> 21], 1u);
    }
    __syncthreads();
    if (tid < 32) warp_suffix_select(hist, 2048, STARGET, &s_dig, &s_rem);
    __syncthreads();
    if (tid == 0) { g_p1[b] = s_dig; g_cnt[b] = 0; g_done[b] = 0; }
}

// ---------------------------------------------------------------------------
// K_B (fused): streaming classify + smem-staged compaction, and the LAST
// chunk-CTA of each batch runs the finisher inline (radix rounds over the
// batch's global candidates, bitmap, dilation, popcount prefix).
// grid (CPB2, B) x 512, dynamic smem union:
//   phase A: cbuf[CBUF_CAP] uint2 (8 KB)
//   phase B: sbm[NWORDS] | hd[NWORDS] (hist aliases hd)  (41.6 KB)
// ---------------------------------------------------------------------------
#define SMEMCF_BYTES (NWORDS * 2 * 4)     // 41600 B > CBUF bytes, covers both
#define WPT2 11                           // 512 * 11 >= 5200

__global__ __launch_bounds__(512) void k_candfin(const float* __restrict__ pred,
                                                 const float* __restrict__ mask)
{
    extern __shared__ uint32_t smem[];
    uint2*    cbuf = (uint2*)smem;        // phase A only
    uint32_t* sbm  = smem;                // phase B only
    uint32_t* hd   = smem + NWORDS;       // phase B only (hist aliases)
    uint32_t* hist = hd;

    __shared__ int scnt, sbase, s_last;
    __shared__ uint32_t s_dig, s_rem;
    __shared__ int swarp[16];
    __shared__ int s_tot;

    const int b = blockIdx.y, chunk = blockIdx.x, tid = threadIdx.x;
    const int lane = tid & 31, wid = tid >> 5;
    const uint32_t p1 = g_p1[b];
    if (tid == 0) scnt = 0;
    __syncthreads();

    // ---- Phase A: classify this chunk ----
    {
        const float4* p4 = (const float4*)(pred + (size_t)b * HW) + chunk * CH4B;
        const float4* m4 = (const float4*)(mask + (size_t)b * HW) + chunk * CH4B;
        const int ibase = chunk * CH4B * 4;

        for (int v = tid; v < CH4B; v += 512) {
            float4 pv = __ldcs(&p4[v]);
            float4 mv = __ldcs(&m4[v]);
            uint32_t kk[4];
            kk[0] = score_key(pv.x, mv.x);
            kk[1] = score_key(pv.y, mv.y);
            kk[2] = score_key(pv.z, mv.z);
            kk[3] = score_key(pv.w, mv.w);
            #pragma unroll
            for (int j = 0; j < 4; j++) {
                if ((kk[j] >> 21) >= p1) {
                    int slot = atomicAdd(&scnt, 1);
                    uint2 cd = make_uint2(kk[j], (uint32_t)(ibase + v * 4 + j));
                    if (slot < CBUF_CAP) {
                        cbuf[slot] = cd;
                    } else {                        // overflow fallback (rare)
                        int g = atomicAdd(&g_cnt[b], 1);
                        if (g < CAND_CAP) g_cand[b][g] = cd;
                    }
                }
            }
        }
        __syncthreads();
        int n = min(scnt, CBUF_CAP);
        if (tid == 0) sbase = atomicAdd(&g_cnt[b], n);
        __syncthreads();
        for (int j = tid; j < n; j += 512) {
            int dst = sbase + j;
            if (dst < CAND_CAP) g_cand[b][dst] = cbuf[j];
        }
    }

    // ---- Last-CTA election ----
    __threadfence();
    __syncthreads();                      // cbuf reads complete before reuse as sbm
    if (tid == 0) s_last = (atomicAdd(&g_done[b], 1) == CPB2 - 1) ? 1 : 0;
    __syncthreads();
    if (!s_last) return;
    __threadfence();                      // see all other CTAs' g_cand writes

    // ---- Phase B: finisher for batch b ----
    const int nc = min(g_cnt[b], CAND_CAP);
    const uint2* cand = g_cand[b];
    uint32_t rem = NA;

    for (int w = tid; w < NWORDS; w += 512) sbm[w] = 0;
    for (int i = tid; i < 2048; i += 512) hist[i] = 0;
    __syncthreads();

    // round 1: bits [21:32)
    for (int j = tid; j < nc; j += 512) atomicAdd(&hist[__ldg(&cand[j].x) >> 21], 1u);
    __syncthreads();
    if (wid == 0) warp_suffix_select(hist, 2048, rem, &s_dig, &s_rem);
    __syncthreads();
    const uint32_t d1 = s_dig; rem = s_rem;
    __syncthreads();

    // round 2: bits [10:21) among digit==d1
    for (int i = tid; i < 2048; i += 512) hist[i] = 0;
    __syncthreads();
    for (int j = tid; j < nc; j += 512) {
        uint32_t k = __ldg(&cand[j].x);
        if ((k >> 21) == d1) atomicAdd(&hist[(k >> 10) & 2047u], 1u);
    }
    __syncthreads();
    if (wid == 0) warp_suffix_select(hist, 2048, rem, &s_dig, &s_rem);
    __syncthreads();
    const uint32_t d2 = s_dig; rem = s_rem;
    __syncthreads();

    // round 3: bits [0:10)
    for (int i = tid; i < 1024; i += 512) hist[i] = 0;
    __syncthreads();
    for (int j = tid; j < nc; j += 512) {
        uint32_t k = __ldg(&cand[j].x);
        if ((k >> 10) == ((d1 << 11) | d2)) atomicAdd(&hist[k & 1023u], 1u);
    }
    __syncthreads();
    if (wid == 0) warp_suffix_select(hist, 1024, rem, &s_dig, &s_rem);
    __syncthreads();
    const uint32_t K = (d1 << 21) | (d2 << 10) | s_dig;
    const uint32_t T = s_rem;
    __syncthreads();

    // mark anchors (stable tie-break by ascending index)
    for (int j = tid; j < nc; j += 512) {
        uint2 cd = __ldg(&cand[j]);
        uint32_t k = cd.x;
        bool anc = false;
        if (k > K) anc = true;
        else if (k == K) {
            uint32_t myi = cd.y, rank = 0;
            for (int t = 0; t < nc; t++) {
                uint2 o = __ldg(&cand[t]);
                if (o.x == K && o.y < myi) rank++;
            }
            if (rank < T) anc = true;
        }
        if (anc) {
            int i = (int)cd.y;
            int r = i / WW, c = i - r * WW;
            atomicOr(&sbm[r * WPR + (c >> 5)], 1u << (c & 31));
        }
    }
    __syncthreads();

    // 5x5 dilation
    for (int w = tid; w < NWORDS; w += 512) {
        int wi = w % WPR;
        uint32_t c    = sbm[w];
        uint32_t prev = (wi > 0)       ? sbm[w - 1] : 0u;
        uint32_t next = (wi < WPR - 1) ? sbm[w + 1] : 0u;
        uint32_t h = c | (c << 1) | (c << 2) | (c >> 1) | (c >> 2)
                   | (prev >> 31) | (prev >> 30) | (next << 31) | (next << 30);
        if (wi == WPR - 1) h &= 0xFFFFu;
        hd[w] = h;
    }
    __syncthreads();
    for (int w = tid; w < NWORDS; w += 512) {
        int r = w / WPR;
        uint32_t vv = hd[w];
        if (r >= 1)   vv |= hd[w - WPR];
        if (r >= 2)   vv |= hd[w - 2 * WPR];
        if (r <= 398) vv |= hd[w + WPR];
        if (r <= 397) vv |= hd[w + 2 * WPR];
        sbm[w] = vv;
        g_dil[b * NWORDS + w] = vv;
    }
    __syncthreads();

    // 2-barrier blocked prefix scan of word popcounts
    {
        const int w0 = tid * WPT2;
        int cnts[WPT2];
        int local = 0;
        #pragma unroll
        for (int k = 0; k < WPT2; k++) {
            int w = w0 + k;
            int c = (w < NWORDS) ? __popc(sbm[w]) : 0;
            cnts[k] = c;
            local += c;
        }
        int incl = local;
        #pragma unroll
        for (int o = 1; o < 32; o <<= 1) {
            int n = __shfl_up_sync(0xffffffffu, incl, o);
            if (lane >= o) incl += n;
        }
        if (lane == 31) swarp[wid] = incl;
        __syncthreads();
        if (wid == 0 && lane < 16) {
            int t = swarp[lane], tv = t;
            #pragma unroll
            for (int o = 1; o < 16; o <<= 1) {
                int n = __shfl_up_sync(0x0000ffffu, tv, o);
                if (lane >= o) tv += n;
            }
            swarp[lane] = tv - t;
            if (lane == 15) s_tot = tv;
        }
        __syncthreads();
        int running = swarp[wid] + (incl - local);
        #pragma unroll
        for (int k = 0; k < WPT2; k++) {
            int w = w0 + k;
            if (w < NWORDS) g_prefix[b * NWORDS + w] = running;
            running += cnts[k];
        }
        if (tid == 0) g_total[b] = s_tot;
    }
}

// ---------------------------------------------------------------------------
// k_write1: one thread per element — new_mask, out_idx, xy, ignore, selgrid.
// ---------------------------------------------------------------------------
__global__ __launch_bounds__(256) void k_write1(const float* __restrict__ grid,
                                                float* __restrict__ out)
{
    const int b = blockIdx.y;
    const int i = blockIdx.x * 256 + threadIdx.x;
    if (i >= HW) return;

    const int r  = i / WW;
    const int c  = i - r * WW;
    const int w  = r * WPR + (c >> 5);
    const int bi = c & 31;

    const uint32_t bits = __ldg(&g_dil[b * NWORDS + w]);
    const int pre       = __ldg(&g_prefix[b * NWORDS + w]);
    const int S         = g_total[b];

    const bool set     = (bits >> bi) & 1u;
    const int  setrank = pre + __popc(bits & ((1u << bi) - 1u));
    const int  pos     = set ? setrank : S + (i - setrank);

    __stcs(&out[NM_OFF + (size_t)b * HW + i], (pos < NP) ? 1.0f : 0.0f);

    if (pos < NP) {
        __stcs(&out[OI_OFF + (size_t)b * NP + pos], (float)i);
        float2 xy = make_float2((float)r, (float)c);
        __stcs((float2*)&out[XY_OFF + ((size_t)b * NP + pos) * 2], xy);
        float2 g = __ldg(&((const float2*)grid)[i]);
        g_selgrid[b][pos] = g;
    } else {
        __stcs(&out[IG_OFF + (size_t)b * NI + (pos - NP)], (float)i);
    }
}

// ---------------------------------------------------------------------------
// k_write2: qp emission, FOUR points (12 floats = 3 aligned float4) / thread.
// ---------------------------------------------------------------------------
__global__ __launch_bounds__(256) void k_write2(const float* __restrict__ zs,
                                                float* __restrict__ out)
{
    const int b = blockIdx.y;
    const int q = blockIdx.x * 256 + threadIdx.x;
    if (q >= 20000) return;
    const int pillar = q / 5000;
    const int t = q - pillar * 5000;
    const float z = __ldg(&zs[pillar]);

    const float4* sg4 = (const float4*)g_selgrid[b];
    float4 a = __ldg(&sg4[2 * t]);
    float4 c = __ldg(&sg4[2 * t + 1]);

    float* dst = out + QP_OFF + (size_t)b * 240000 + (size_t)pillar * 60000 + 12 * t;
    __stcs((float4*)(dst),     make_float4(a.x, a.y, z, a.z));
    __stcs((float4*)(dst + 4), make_float4(a.w, z, c.x, c.y));
    __stcs((float4*)(dst + 8), make_float4(z, c.z, c.w, z));
}

// ---------------------------------------------------------------------------
extern "C" void kernel_launch(void* const* d_in, const int* in_sizes, int n_in,
                              void* d_out, int out_size)
{
    const float* pred = nullptr;
    const float* mask = nullptr;
    const float* grid = nullptr;
    const float* zs   = nullptr;
    for (int i = 0; i < n_in; i++) {
        if (in_sizes[i] == B * HW) {
            if (!pred) pred = (const float*)d_in[i];
            else if (!mask) mask = (const float*)d_in[i];
        } else if (in_sizes[i] == HW * 2) {
            grid = (const float*)d_in[i];
        } else if (in_sizes[i] == 4) {
            zs = (const float*)d_in[i];
        }
    }
    float* out = (float*)d_out;

    k_sample<<<B, 256>>>(pred, mask);
    dim3 gc(CPB2, B);
    k_candfin<<<gc, 512, SMEMCF_BYTES>>>(pred, mask);
    dim3 gw1((HW + 255) / 256, B);
    k_write1<<<gw1, 256>>>(grid, out);
    dim3 gw2((20000 + 255) / 256, B);
    k_write2<<<gw2, 256>>>(zs, out);
}

// round 14
// speedup vs baseline: 1.6334x; 1.6334x over previous
#include <cuda_runtime.h>
#include <cstdint>
#include <math_constants.h>

#define B      128
#define HH     400
#define WW     400
#define HW     160000
#define WPR    13
#define NWORDS 5200
#define NA     2500
#define NP     20000
#define NI     (HW - NP)
#define CAND_CAP 16384
#define SBUF_CAP 4096
// sampling: 12.5% in coalesced runs of 32 float4 per 256-float4 window
#define NS4    5000
#define STARGET 625
// candidate pass chunking
#define CPB2   20
#define CH4B   (HW / 4 / CPB2)      // 2000

// Output layout: flat f32 concat of (out_idx, query_pos, new_mask, xy_vox_idx, ignore_idx)
#define OI_OFF 0l
#define QP_OFF 2560000l
#define NM_OFF 33280000l
#define XY_OFF 53760000l
#define IG_OFF 58880000l

__device__ uint32_t g_p1[B];
__device__ int      g_cnt[B];
__device__ uint2    g_cand[B][CAND_CAP];      // {key, idx}
__device__ uint32_t g_dil[B * NWORDS];
__device__ int      g_prefix[B * NWORDS];
__device__ int      g_total[B];

__device__ __forceinline__ uint32_t mono_key(float v) {
    uint32_t u = __float_as_uint(v);
    return (u & 0x80000000u) ? ~u : (u | 0x80000000u);
}

__device__ __forceinline__ uint32_t score_key(float p, float m) {
    if (m == 1.0f) return mono_key(p);
    if (m == 0.0f) return mono_key(-CUDART_INF_F);
    float s = __fdividef(1.0f, 1.0f + __expf(-p)) * m;
    float pe;
    if (s <= 0.0f)      pe = -CUDART_INF_F;
    else if (s >= 1.0f) pe =  CUDART_INF_F;
    else                pe = __logf(s) - __logf(1.0f - s);
    return mono_key(pe);
}

// Warp-serial suffix select (warp 0 only). Largest digit d with
// sum_{d'>=d} hist[d'] >= rem; *s_rem = rem - sum_{d'>d}.
__device__ __forceinline__ void warp_suffix_select(const uint32_t* hist, int nbins,
                                                   uint32_t rem,
                                                   volatile uint32_t* s_dig,
                                                   volatile uint32_t* s_rem)
{
    const int lane = threadIdx.x & 31;
    const int per = nbins >> 5;
    uint32_t lsum = 0;
    for (int k = 0; k < per; k++) {
        int kk = (k + lane) & (per - 1);          // rotated -> conflict-free
        lsum += hist[lane * per + kk];
    }
    uint32_t suf = lsum;
    #pragma unroll
    for (int o = 1; o < 32; o <<= 1) {
        uint32_t n = __shfl_down_sync(0xffffffffu, suf, o);
        if (lane + o < 32) suf += n;
    }
    uint32_t sufnext = suf - lsum;
    bool mine = (suf >= rem) && (sufnext < rem);
    if (mine) {
        uint32_t acc = sufnext;
        for (int k = per - 1; k >= 0; k--) {
            uint32_t h = hist[lane * per + k];
            acc += h;
            if (acc >= rem) { *s_dig = (uint32_t)(lane * per + k); *s_rem = rem - (acc - h); break; }
        }
    }
}

// ---------------------------------------------------------------------------
// K_A: sampled histogram (coalesced 32-float4 runs, 12.5%) -> conservative
// pivot digit. grid B x 256
// ---------------------------------------------------------------------------
__global__ __launch_bounds__(256) void k_sample(const float* __restrict__ pred,
                                                const float* __restrict__ mask)
{
    __shared__ uint32_t hist[2048];
    __shared__ uint32_t s_dig, s_rem;
    const int b = blockIdx.x, tid = threadIdx.x;
    for (int i = tid; i < 2048; i += 256) hist[i] = 0;
    __syncthreads();

    const float4* p4 = (const float4*)(pred + (size_t)b * HW);
    const float4* m4 = (const float4*)(mask + (size_t)b * HW);
    for (int s = tid; s < NS4; s += 256) {
        int v = ((s & ~31) << 3) + (s & 31);      // 32-consecutive runs, coalesced
        float4 pv = __ldg(&p4[v]);
        float4 mv = __ldg(&m4[v]);
        atomicAdd(&hist[score_key(pv.x, mv.x) >> 21], 1u);
        atomicAdd(&hist[score_key(pv.y, mv.y) >> 21], 1u);
        atomicAdd(&hist[score_key(pv.z, mv.z) >> 21], 1u);
        atomicAdd(&hist[score_key(pv.w, mv.w) >> 21], 1u);
    }
    __syncthreads();
    if (tid < 32) warp_suffix_select(hist, 2048, STARGET, &s_dig, &s_rem);
    __syncthreads();
    if (tid == 0) { g_p1[b] = s_dig; g_cnt[b] = 0; }
}

// ---------------------------------------------------------------------------
// K_B: streaming classify with smem-staged candidate compaction.
// ONE global atomicAdd per CTA. grid (CPB2, B) x 256
// ---------------------------------------------------------------------------
__global__ __launch_bounds__(256) void k_cand(const float* __restrict__ pred,
                                              const float* __restrict__ mask)
{
    __shared__ uint2 cbuf[SBUF_CAP];
    __shared__ int scnt, sbase;
    const int b = blockIdx.y, chunk = blockIdx.x, tid = threadIdx.x;
    const uint32_t p1 = g_p1[b];
    if (tid == 0) scnt = 0;
    __syncthreads();

    const float4* p4 = (const float4*)(pred + (size_t)b * HW) + chunk * CH4B;
    const float4* m4 = (const float4*)(mask + (size_t)b * HW) + chunk * CH4B;
    const int ibase = chunk * CH4B * 4;

    for (int v = tid; v < CH4B; v += 256) {
        float4 pv = __ldcs(&p4[v]);
        float4 mv = __ldcs(&m4[v]);
        uint32_t kk[4];
        kk[0] = score_key(pv.x, mv.x);
        kk[1] = score_key(pv.y, mv.y);
        kk[2] = score_key(pv.z, mv.z);
        kk[3] = score_key(pv.w, mv.w);
        #pragma unroll
        for (int j = 0; j < 4; j++) {
            if ((kk[j] >> 21) >= p1) {
                int slot = atomicAdd(&scnt, 1);
                uint2 cd = make_uint2(kk[j], (uint32_t)(ibase + v * 4 + j));
                if (slot < SBUF_CAP) {
                    cbuf[slot] = cd;
                } else {                            // overflow fallback (rare)
                    int g = atomicAdd(&g_cnt[b], 1);
                    if (g < CAND_CAP) g_cand[b][g] = cd;
                }
            }
        }
    }
    __syncthreads();
    int n = min(scnt, SBUF_CAP);
    if (tid == 0) sbase = atomicAdd(&g_cnt[b], n);
    __syncthreads();
    for (int j = tid; j < n; j += 256) {
        int dst = sbase + j;
        if (dst < CAND_CAP) g_cand[b][dst] = cbuf[j];
    }
}

// ---------------------------------------------------------------------------
// K_fin: exact top-NA among candidates (3 radix rounds in smem), bitmap,
// dilation, 2-barrier popcount prefix. grid B x 1024.
// smem: sbm[NWORDS] | hd[NWORDS] (aliases hist) | candk[CAP] | candi[CAP]
// total = 172,672 B < 227 KB limit.
// ---------------------------------------------------------------------------
#define SMEMF_BYTES ((NWORDS + NWORDS + CAND_CAP + CAND_CAP) * 4)
#define WPT 6

__global__ __launch_bounds__(1024) void k_fin()
{
    extern __shared__ uint32_t smem[];
    uint32_t* sbm    = smem;
    uint32_t* hd     = sbm + NWORDS;
    uint32_t* candk  = hd + NWORDS;
    uint32_t* candis = candk + CAND_CAP;
    uint32_t* hist   = hd;

    __shared__ uint32_t s_dig, s_rem;
    __shared__ int swarp[32];
    __shared__ int s_tot;

    const int b = blockIdx.x, tid = threadIdx.x, lane = tid & 31, wid = tid >> 5;
    uint32_t rem = NA;
    const int nc = min(g_cnt[b], CAND_CAP);

    for (int w = tid; w < NWORDS; w += 1024) sbm[w] = 0;
    for (int i = tid; i < 2048; i += 1024) hist[i] = 0;
    for (int j = tid; j < nc; j += 1024) {
        uint2 cd = g_cand[b][j];
        candk[j] = cd.x;
        candis[j] = cd.y;
    }
    __syncthreads();

    // round 1: bits [21:32)
    for (int j = tid; j < nc; j += 1024) atomicAdd(&hist[candk[j] >> 21], 1u);
    __syncthreads();
    if (wid == 0) warp_suffix_select(hist, 2048, rem, &s_dig, &s_rem);
    __syncthreads();
    const uint32_t d1 = s_dig; rem = s_rem;
    __syncthreads();

    // round 2: bits [10:21) among digit==d1
    for (int i = tid; i < 2048; i += 1024) hist[i] = 0;
    __syncthreads();
    for (int j = tid; j < nc; j += 1024) {
        uint32_t k = candk[j];
        if ((k >> 21) == d1) atomicAdd(&hist[(k >> 10) & 2047u], 1u);
    }
    __syncthreads();
    if (wid == 0) warp_suffix_select(hist, 2048, rem, &s_dig, &s_rem);
    __syncthreads();
    const uint32_t d2 = s_dig; rem = s_rem;
    __syncthreads();

    // round 3: bits [0:10)
    hist[tid] = 0;
    __syncthreads();
    for (int j = tid; j < nc; j += 1024) {
        uint32_t k = candk[j];
        if ((k >> 10) == ((d1 << 11) | d2)) atomicAdd(&hist[k & 1023u], 1u);
    }
    __syncthreads();
    if (wid == 0) warp_suffix_select(hist, 1024, rem, &s_dig, &s_rem);
    __syncthreads();
    const uint32_t K = (d1 << 21) | (d2 << 10) | s_dig;
    const uint32_t T = s_rem;
    __syncthreads();

    // mark anchors (stable tie-break by ascending index)
    for (int j = tid; j < nc; j += 1024) {
        uint32_t k = candk[j];
        bool anc = false;
        if (k > K) anc = true;
        else if (k == K) {
            uint32_t myi = candis[j], rank = 0;
            for (int t = 0; t < nc; t++)
                if (candk[t] == K && candis[t] < myi) rank++;
            if (rank < T) anc = true;
        }
        if (anc) {
            int i = (int)candis[j];
            int r = i / WW, c = i - r * WW;
            atomicOr(&sbm[r * WPR + (c >> 5)], 1u << (c & 31));
        }
    }
    __syncthreads();

    // 5x5 dilation
    for (int w = tid; w < NWORDS; w += 1024) {
        int wi = w % WPR;
        uint32_t c    = sbm[w];
        uint32_t prev = (wi > 0)       ? sbm[w - 1] : 0u;
        uint32_t next = (wi < WPR - 1) ? sbm[w + 1] : 0u;
        uint32_t h = c | (c << 1) | (c << 2) | (c >> 1) | (c >> 2)
                   | (prev >> 31) | (prev >> 30) | (next << 31) | (next << 30);
        if (wi == WPR - 1) h &= 0xFFFFu;
        hd[w] = h;
    }
    __syncthreads();
    for (int w = tid; w < NWORDS; w += 1024) {
        int r = w / WPR;
        uint32_t vv = hd[w];
        if (r >= 1)   vv |= hd[w - WPR];
        if (r >= 2)   vv |= hd[w - 2 * WPR];
        if (r <= 398) vv |= hd[w + WPR];
        if (r <= 397) vv |= hd[w + 2 * WPR];
        sbm[w] = vv;
        g_dil[b * NWORDS + w] = vv;
    }
    __syncthreads();

    // 2-barrier blocked prefix scan of word popcounts
    {
        const int w0 = tid * WPT;
        int cnts[WPT];
        int local = 0;
        #pragma unroll
        for (int k = 0; k < WPT; k++) {
            int w = w0 + k;
            int c = (w < NWORDS) ? __popc(sbm[w]) : 0;
            cnts[k] = c;
            local += c;
        }
        int incl = local;
        #pragma unroll
        for (int o = 1; o < 32; o <<= 1) {
            int n = __shfl_up_sync(0xffffffffu, incl, o);
            if (lane >= o) incl += n;
        }
        if (lane == 31) swarp[wid] = incl;
        __syncthreads();
        if (wid == 0) {
            int t = swarp[lane], tv = t;
            #pragma unroll
            for (int o = 1; o < 32; o <<= 1) {
                int n = __shfl_up_sync(0xffffffffu, tv, o);
                if (lane >= o) tv += n;
            }
            swarp[lane] = tv - t;
            if (lane == 31) s_tot = tv;
        }
        __syncthreads();
        int running = swarp[wid] + (incl - local);
        #pragma unroll
        for (int k = 0; k < WPT; k++) {
            int w = w0 + k;
            if (w < NWORDS) g_prefix[b * NWORDS + w] = running;
            running += cnts[k];
        }
        if (tid == 0) g_total[b] = s_tot;
    }
}

// ---------------------------------------------------------------------------
// k_write: single fused writer — one thread per element, ALL 5 outputs.
// pos(i) = setrank(i) if set else S + (i - setrank(i))
// (Measured 92 µs in this form vs 107 µs for the write1/write2 split.)
// ---------------------------------------------------------------------------
__global__ __launch_bounds__(256) void k_write(const float* __restrict__ grid,
                                               const float* __restrict__ zs,
                                               float* __restrict__ out)
{
    const int b = blockIdx.y;
    const int i = blockIdx.x * 256 + threadIdx.x;
    if (i >= HW) return;

    const int r  = i / WW;
    const int c  = i - r * WW;
    const int w  = r * WPR + (c >> 5);
    const int bi = c & 31;

    const uint32_t bits = __ldg(&g_dil[b * NWORDS + w]);
    const int pre       = __ldg(&g_prefix[b * NWORDS + w]);
    const int S         = g_total[b];

    const bool set     = (bits >> bi) & 1u;
    const int  setrank = pre + __popc(bits & ((1u << bi) - 1u));
    const int  pos     = set ? setrank : S + (i - setrank);

    __stcs(&out[NM_OFF + (size_t)b * HW + i], (pos < NP) ? 1.0f : 0.0f);

    if (pos < NP) {
        __stcs(&out[OI_OFF + (size_t)b * NP + pos], (float)i);
        float2 xy = make_float2((float)r, (float)c);
        __stcs((float2*)&out[XY_OFF + ((size_t)b * NP + pos) * 2], xy);
        float2 g = __ldg(&((const float2*)grid)[i]);
        float z0 = __ldg(&zs[0]), z1 = __ldg(&zs[1]), z2 = __ldg(&zs[2]), z3 = __ldg(&zs[3]);
        size_t qb = QP_OFF + (size_t)b * 240000 + (size_t)pos * 3;
        __stcs(&out[qb],          g.x); __stcs(&out[qb + 1],      g.y); __stcs(&out[qb + 2],      z0);
        __stcs(&out[qb + 60000],  g.x); __stcs(&out[qb + 60001],  g.y); __stcs(&out[qb + 60002],  z1);
        __stcs(&out[qb + 120000], g.x); __stcs(&out[qb + 120001], g.y); __stcs(&out[qb + 120002], z2);
        __stcs(&out[qb + 180000], g.x); __stcs(&out[qb + 180001], g.y); __stcs(&out[qb + 180002], z3);
    } else {
        __stcs(&out[IG_OFF + (size_t)b * NI + (pos - NP)], (float)i);
    }
}

// ---------------------------------------------------------------------------
extern "C" void kernel_launch(void* const* d_in, const int* in_sizes, int n_in,
                              void* d_out, int out_size)
{
    const float* pred = nullptr;
    const float* mask = nullptr;
    const float* grid = nullptr;
    const float* zs   = nullptr;
    for (int i = 0; i < n_in; i++) {
        if (in_sizes[i] == B * HW) {
            if (!pred) pred = (const float*)d_in[i];
            else if (!mask) mask = (const float*)d_in[i];
        } else if (in_sizes[i] == HW * 2) {
            grid = (const float*)d_in[i];
        } else if (in_sizes[i] == 4) {
            zs = (const float*)d_in[i];
        }
    }
    float* out = (float*)d_out;

    cudaFuncSetAttribute(k_fin, cudaFuncAttributeMaxDynamicSharedMemorySize, SMEMF_BYTES);

    k_sample<<<B, 256>>>(pred, mask);
    dim3 gc(CPB2, B);
    k_cand<<<gc, 256>>>(pred, mask);
    k_fin<<<B, 1024, SMEMF_BYTES>>>();
    dim3 gw((HW + 255) / 256, B);
    k_write<<<gw, 256>>>(grid, zs, out);
}

// round 15
// speedup vs baseline: 2.5546x; 1.5640x over previous
#include <cuda_runtime.h>
#include <cstdint>
#include <math_constants.h>

#define B      128
#define HH     400
#define WW     400
#define HW     160000
#define WPR    13
#define NWORDS 5200
#define NA     2500
#define NP     20000
#define NI     (HW - NP)
#define CAND_CAP 16384
#define SBUF_CAP 4096
#define TIE_CAP 256
// sampling: 6.25% in coalesced runs of 32 float4 per 512-float4 window
#define NS4    2500
#define STARGET 313
// candidate pass chunking
#define CPB2   20
#define CH4B   (HW / 4 / CPB2)      // 2000

// Output layout: flat f32 concat of (out_idx, query_pos, new_mask, xy_vox_idx, ignore_idx)
#define OI_OFF 0l
#define QP_OFF 2560000l
#define NM_OFF 33280000l
#define XY_OFF 53760000l
#define IG_OFF 58880000l

__device__ uint32_t g_p1[B];
__device__ int      g_cnt[B];
__device__ uint2    g_cand[B][CAND_CAP];      // {key, idx}
__device__ uint32_t g_dil[B * NWORDS];
__device__ int      g_prefix[B * NWORDS];
__device__ int      g_total[B];

__device__ __forceinline__ uint32_t mono_key(float v) {
    uint32_t u = __float_as_uint(v);
    return (u & 0x80000000u) ? ~u : (u | 0x80000000u);
}

__device__ __forceinline__ uint32_t score_key(float p, float m) {
    if (m == 1.0f) return mono_key(p);
    if (m == 0.0f) return mono_key(-CUDART_INF_F);
    float s = __fdividef(1.0f, 1.0f + __expf(-p)) * m;
    float pe;
    if (s <= 0.0f)      pe = -CUDART_INF_F;
    else if (s >= 1.0f) pe =  CUDART_INF_F;
    else                pe = __logf(s) - __logf(1.0f - s);
    return mono_key(pe);
}

// Warp-serial suffix select (warp 0 only). Largest digit d with
// sum_{d'>=d} hist[d'] >= rem; *s_rem = rem - sum_{d'>d}.
__device__ __forceinline__ void warp_suffix_select(const uint32_t* hist, int nbins,
                                                   uint32_t rem,
                                                   volatile uint32_t* s_dig,
                                                   volatile uint32_t* s_rem)
{
    const int lane = threadIdx.x & 31;
    const int per = nbins >> 5;
    uint32_t lsum = 0;
    for (int k = 0; k < per; k++) {
        int kk = (k + lane) & (per - 1);          // rotated -> conflict-free
        lsum += hist[lane * per + kk];
    }
    uint32_t suf = lsum;
    #pragma unroll
    for (int o = 1; o < 32; o <<= 1) {
        uint32_t n = __shfl_down_sync(0xffffffffu, suf, o);
        if (lane + o < 32) suf += n;
    }
    uint32_t sufnext = suf - lsum;
    bool mine = (suf >= rem) && (sufnext < rem);
    if (mine) {
        uint32_t acc = sufnext;
        for (int k = per - 1; k >= 0; k--) {
            uint32_t h = hist[lane * per + k];
            acc += h;
            if (acc >= rem) { *s_dig = (uint32_t)(lane * per + k); *s_rem = rem - (acc - h); break; }
        }
    }
}

// ---------------------------------------------------------------------------
// K_A: sampled histogram (coalesced 32-float4 runs, 6.25%) -> conservative
// pivot digit. grid B x 256
// ---------------------------------------------------------------------------
__global__ __launch_bounds__(256) void k_sample(const float* __restrict__ pred,
                                                const float* __restrict__ mask)
{
    __shared__ uint32_t hist[2048];
    __shared__ uint32_t s_dig, s_rem;
    const int b = blockIdx.x, tid = threadIdx.x;
    for (int i = tid; i < 2048; i += 256) hist[i] = 0;
    __syncthreads();

    const float4* p4 = (const float4*)(pred + (size_t)b * HW);
    const float4* m4 = (const float4*)(mask + (size_t)b * HW);
    for (int s = tid; s < NS4; s += 256) {
        int v = ((s & ~31) << 4) + (s & 31);      // 32-consecutive runs, 1/16 rate
        float4 pv = __ldg(&p4[v]);
        float4 mv = __ldg(&m4[v]);
        atomicAdd(&hist[score_key(pv.x, mv.x) >> 21], 1u);
        atomicAdd(&hist[score_key(pv.y, mv.y) >> 21], 1u);
        atomicAdd(&hist[score_key(pv.z, mv.z) >> 21], 1u);
        atomicAdd(&hist[score_key(pv.w, mv.w) >> 21], 1u);
    }
    __syncthreads();
    if (tid < 32) warp_suffix_select(hist, 2048, STARGET, &s_dig, &s_rem);
    __syncthreads();
    if (tid == 0) { g_p1[b] = s_dig; g_cnt[b] = 0; }
}

// ---------------------------------------------------------------------------
// K_B: streaming classify with smem-staged candidate compaction.
// 2 float4 per thread per iteration (32B/thread, doubled MLP).
// ONE global atomicAdd per CTA. grid (CPB2, B) x 256
// ---------------------------------------------------------------------------
__global__ __launch_bounds__(256) void k_cand(const float* __restrict__ pred,
                                              const float* __restrict__ mask)
{
    __shared__ uint2 cbuf[SBUF_CAP];
    __shared__ int scnt, sbase;
    const int b = blockIdx.y, chunk = blockIdx.x, tid = threadIdx.x;
    const uint32_t p1 = g_p1[b];
    if (tid == 0) scnt = 0;
    __syncthreads();

    const float4* p4 = (const float4*)(pred + (size_t)b * HW) + chunk * CH4B;
    const float4* m4 = (const float4*)(mask + (size_t)b * HW) + chunk * CH4B;
    const int ibase = chunk * CH4B * 4;

    for (int v0 = tid * 2; v0 < CH4B; v0 += 512) {
        float4 pv0 = __ldcs(&p4[v0]);
        float4 pv1 = __ldcs(&p4[v0 + 1]);
        float4 mv0 = __ldcs(&m4[v0]);
        float4 mv1 = __ldcs(&m4[v0 + 1]);
        uint32_t kk[8];
        kk[0] = score_key(pv0.x, mv0.x);
        kk[1] = score_key(pv0.y, mv0.y);
        kk[2] = score_key(pv0.z, mv0.z);
        kk[3] = score_key(pv0.w, mv0.w);
        kk[4] = score_key(pv1.x, mv1.x);
        kk[5] = score_key(pv1.y, mv1.y);
        kk[6] = score_key(pv1.z, mv1.z);
        kk[7] = score_key(pv1.w, mv1.w);
        #pragma unroll
        for (int j = 0; j < 8; j++) {
            if ((kk[j] >> 21) >= p1) {
                int slot = atomicAdd(&scnt, 1);
                uint2 cd = make_uint2(kk[j], (uint32_t)(ibase + v0 * 4 + j));
                if (slot < SBUF_CAP) {
                    cbuf[slot] = cd;
                } else {                            // overflow fallback (rare)
                    int g = atomicAdd(&g_cnt[b], 1);
                    if (g < CAND_CAP) g_cand[b][g] = cd;
                }
            }
        }
    }
    __syncthreads();
    int n = min(scnt, SBUF_CAP);
    if (tid == 0) sbase = atomicAdd(&g_cnt[b], n);
    __syncthreads();
    for (int j = tid; j < n; j += 256) {
        int dst = sbase + j;
        if (dst < CAND_CAP) g_cand[b][dst] = cbuf[j];
    }
}

// ---------------------------------------------------------------------------
// K_fin: exact top-NA among candidates (3 radix rounds in smem), O(1) tie
// resolution, bitmap, dilation, 2-barrier popcount prefix. grid B x 1024.
// smem: sbm[NWORDS] | hd[NWORDS] (aliases hist) | candk[CAP] | candi[CAP]
// ---------------------------------------------------------------------------
#define SMEMF_BYTES ((NWORDS + NWORDS + CAND_CAP + CAND_CAP) * 4)
#define WPT 6

__global__ __launch_bounds__(1024) void k_fin()
{
    extern __shared__ uint32_t smem[];
    uint32_t* sbm    = smem;
    uint32_t* hd     = sbm + NWORDS;
    uint32_t* candk  = hd + NWORDS;
    uint32_t* candis = candk + CAND_CAP;
    uint32_t* hist   = hd;

    __shared__ uint32_t s_dig, s_rem;
    __shared__ int swarp[32];
    __shared__ int s_tot;
    __shared__ uint32_t tie_idx[TIE_CAP];
    __shared__ int tie_n;

    const int b = blockIdx.x, tid = threadIdx.x, lane = tid & 31, wid = tid >> 5;
    uint32_t rem = NA;
    const int nc = min(g_cnt[b], CAND_CAP);

    for (int w = tid; w < NWORDS; w += 1024) sbm[w] = 0;
    for (int i = tid; i < 2048; i += 1024) hist[i] = 0;
    if (tid == 0) tie_n = 0;
    for (int j = tid; j < nc; j += 1024) {
        uint2 cd = g_cand[b][j];
        candk[j] = cd.x;
        candis[j] = cd.y;
    }
    __syncthreads();

    // round 1: bits [21:32)
    for (int j = tid; j < nc; j += 1024) atomicAdd(&hist[candk[j] >> 21], 1u);
    __syncthreads();
    if (wid == 0) warp_suffix_select(hist, 2048, rem, &s_dig, &s_rem);
    __syncthreads();
    const uint32_t d1 = s_dig; rem = s_rem;
    __syncthreads();

    // round 2: bits [10:21) among digit==d1
    for (int i = tid; i < 2048; i += 1024) hist[i] = 0;
    __syncthreads();
    for (int j = tid; j < nc; j += 1024) {
        uint32_t k = candk[j];
        if ((k >> 21) == d1) atomicAdd(&hist[(k >> 10) & 2047u], 1u);
    }
    __syncthreads();
    if (wid == 0) warp_suffix_select(hist, 2048, rem, &s_dig, &s_rem);
    __syncthreads();
    const uint32_t d2 = s_dig; rem = s_rem;
    __syncthreads();

    // round 3: bits [0:10)
    hist[tid] = 0;
    __syncthreads();
    for (int j = tid; j < nc; j += 1024) {
        uint32_t k = candk[j];
        if ((k >> 10) == ((d1 << 11) | d2)) atomicAdd(&hist[k & 1023u], 1u);
    }
    __syncthreads();
    if (wid == 0) warp_suffix_select(hist, 1024, rem, &s_dig, &s_rem);
    __syncthreads();
    const uint32_t K = (d1 << 21) | (d2 << 10) | s_dig;
    const uint32_t T = s_rem;
    __syncthreads();

    // mark anchors; collect ties (key == K) into tiny list
    for (int j = tid; j < nc; j += 1024) {
        uint32_t k = candk[j];
        if (k > K) {
            int i = (int)candis[j];
            int r = i / WW, c = i - r * WW;
            atomicOr(&sbm[r * WPR + (c >> 5)], 1u << (c & 31));
        } else if (k == K) {
            int t = atomicAdd(&tie_n, 1);
            if (t < TIE_CAP) tie_idx[t] = candis[j];
        }
    }
    __syncthreads();
    // rank ties by ascending index; take first T
    {
        int tn = min(tie_n, TIE_CAP);
        if (tid < tn) {
            uint32_t myi = tie_idx[tid];
            int rank = 0;
            for (int t = 0; t < tn; t++) rank += (tie_idx[t] < myi);
            if ((uint32_t)rank < T) {
                int i = (int)myi;
                int r = i / WW, c = i - r * WW;
                atomicOr(&sbm[r * WPR + (c >> 5)], 1u << (c & 31));
            }
        }
    }
    __syncthreads();

    // 5x5 dilation
    for (int w = tid; w < NWORDS; w += 1024) {
        int wi = w % WPR;
        uint32_t c    = sbm[w];
        uint32_t prev = (wi > 0)       ? sbm[w - 1] : 0u;
        uint32_t next = (wi < WPR - 1) ? sbm[w + 1] : 0u;
        uint32_t h = c | (c << 1) | (c << 2) | (c >> 1) | (c >> 2)
                   | (prev >> 31) | (prev >> 30) | (next << 31) | (next << 30);
        if (wi == WPR - 1) h &= 0xFFFFu;
        hd[w] = h;
    }
    __syncthreads();
    for (int w = tid; w < NWORDS; w += 1024) {
        int r = w / WPR;
        uint32_t vv = hd[w];
        if (r >= 1)   vv |= hd[w - WPR];
        if (r >= 2)   vv |= hd[w - 2 * WPR];
        if (r <= 398) vv |= hd[w + WPR];
        if (r <= 397) vv |= hd[w + 2 * WPR];
        sbm[w] = vv;
        g_dil[b * NWORDS + w] = vv;
    }
    __syncthreads();

    // 2-barrier blocked prefix scan of word popcounts
    {
        const int w0 = tid * WPT;
        int cnts[WPT];
        int local = 0;
        #pragma unroll
        for (int k = 0; k < WPT; k++) {
            int w = w0 + k;
            int c = (w < NWORDS) ? __popc(sbm[w]) : 0;
            cnts[k] = c;
            local += c;
        }
        int incl = local;
        #pragma unroll
        for (int o = 1; o < 32; o <<= 1) {
            int n = __shfl_up_sync(0xffffffffu, incl, o);
            if (lane >= o) incl += n;
        }
        if (lane == 31) swarp[wid] = incl;
        __syncthreads();
        if (wid == 0) {
            int t = swarp[lane], tv = t;
            #pragma unroll
            for (int o = 1; o < 32; o <<= 1) {
                int n = __shfl_up_sync(0xffffffffu, tv, o);
                if (lane >= o) tv += n;
            }
            swarp[lane] = tv - t;
            if (lane == 31) s_tot = tv;
        }
        __syncthreads();
        int running = swarp[wid] + (incl - local);
        #pragma unroll
        for (int k = 0; k < WPT; k++) {
            int w = w0 + k;
            if (w < NWORDS) g_prefix[b * NWORDS + w] = running;
            running += cnts[k];
        }
        if (tid == 0) g_total[b] = s_tot;
    }
}

// ---------------------------------------------------------------------------
// k_write: single fused writer — one thread per element, ALL 5 outputs.
// ---------------------------------------------------------------------------
__global__ __launch_bounds__(256) void k_write(const float* __restrict__ grid,
                                               const float* __restrict__ zs,
                                               float* __restrict__ out)
{
    const int b = blockIdx.y;
    const int i = blockIdx.x * 256 + threadIdx.x;
    if (i >= HW) return;

    const int r  = i / WW;
    const int c  = i - r * WW;
    const int w  = r * WPR + (c >> 5);
    const int bi = c & 31;

    const uint32_t bits = __ldg(&g_dil[b * NWORDS + w]);
    const int pre       = __ldg(&g_prefix[b * NWORDS + w]);
    const int S         = g_total[b];

    const bool set     = (bits >> bi) & 1u;
    const int  setrank = pre + __popc(bits & ((1u << bi) - 1u));
    const int  pos     = set ? setrank : S + (i - setrank);

    __stcs(&out[NM_OFF + (size_t)b * HW + i], (pos < NP) ? 1.0f : 0.0f);

    if (pos < NP) {
        __stcs(&out[OI_OFF + (size_t)b * NP + pos], (float)i);
        float2 xy = make_float2((float)r, (float)c);
        __stcs((float2*)&out[XY_OFF + ((size_t)b * NP + pos) * 2], xy);
        float2 g = __ldg(&((const float2*)grid)[i]);
        float z0 = __ldg(&zs[0]), z1 = __ldg(&zs[1]), z2 = __ldg(&zs[2]), z3 = __ldg(&zs[3]);
        size_t qb = QP_OFF + (size_t)b * 240000 + (size_t)pos * 3;
        __stcs(&out[qb],          g.x); __stcs(&out[qb + 1],      g.y); __stcs(&out[qb + 2],      z0);
        __stcs(&out[qb + 60000],  g.x); __stcs(&out[qb + 60001],  g.y); __stcs(&out[qb + 60002],  z1);
        __stcs(&out[qb + 120000], g.x); __stcs(&out[qb + 120001], g.y); __stcs(&out[qb + 120002], z2);
        __stcs(&out[qb + 180000], g.x); __stcs(&out[qb + 180001], g.y); __stcs(&out[qb + 180002], z3);
    } else {
        __stcs(&out[IG_OFF + (size_t)b * NI + (pos - NP)], (float)i);
    }
}

// ---------------------------------------------------------------------------
extern "C" void kernel_launch(void* const* d_in, const int* in_sizes, int n_in,
                              void* d_out, int out_size)
{
    const float* pred = nullptr;
    const float* mask = nullptr;
    const float* grid = nullptr;
    const float* zs   = nullptr;
    for (int i = 0; i < n_in; i++) {
        if (in_sizes[i] == B * HW) {
            if (!pred) pred = (const float*)d_in[i];
            else if (!mask) mask = (const float*)d_in[i];
        } else if (in_sizes[i] == HW * 2) {
            grid = (const float*)d_in[i];
        } else if (in_sizes[i] == 4) {
            zs = (const float*)d_in[i];
        }
    }
    float* out = (float*)d_out;

    cudaFuncSetAttribute(k_fin, cudaFuncAttributeMaxDynamicSharedMemorySize, SMEMF_BYTES);

    k_sample<<<B, 256>>>(pred, mask);
    dim3 gc(CPB2, B);
    k_cand<<<gc, 256>>>(pred, mask);
    k_fin<<<B, 1024, SMEMF_BYTES>>>();
    dim3 gw((HW + 255) / 256, B);
    k_write<<<gw, 256>>>(grid, zs, out);
}